// round 5
// baseline (speedup 1.0000x reference)
#include <cuda_runtime.h>

#define NN 8192
#define KK 64
#define DD 256
#define HH 128
#define K1_GRID     512
#define K1_THREADS  256
#define K1_FILLROWS 3072          // adj rows zero-filled by kernel 1 (96 MB)

// ---- flat fp32 output layout (concat of reference tuple) ----
#define OFF_ADJ    0LL
#define OFF_FEAT   ((long long)NN * NN)
#define OFF_PROB   (OFF_FEAT + (long long)NN * DD)
#define OFF_PAIR   (OFF_PROB + (long long)NN * KK * 2)
#define OFF_BEFORE (OFF_PAIR + (long long)NN * KK * 2)
#define OFF_AFTER  (OFF_BEFORE + 1)
#define OFF_LEFT   (OFF_AFTER + 1)

// scratch: featW = feat @ W1   [N, 128]  (4 MB, L2-resident for edge gather)
__device__ float g_featW[(size_t)NN * HH];

// ---------------------------------------------------------------------------
// Kernel 1: featW = feat @ W1, warp-local (no block syncs, no W1 staging —
// W1 is 128 KB and lives in L1 since every warp streams the same addresses).
// 8 warps/block, 2 rows/warp, grid 512 (~3.5 blocks/SM resident).
// Fused: feat copy to out + 6 adj rows zero-fill per block (96 MB total).
// ---------------------------------------------------------------------------
__global__ void __launch_bounds__(K1_THREADS) featw_kernel(const float* __restrict__ feat,
                                                           const float* __restrict__ W1,
                                                           float* __restrict__ out) {
    __shared__ __align__(16) float srow[8][2 * DD];   // 16 KB

    const int tid  = threadIdx.x;
    const int warp = tid >> 5;
    const int lane = tid & 31;

    // ---- streaming zero-fill: 6 adj rows per block (192 KB), no deps
    {
        const float4 z = make_float4(0.f, 0.f, 0.f, 0.f);
        float4* dst = reinterpret_cast<float4*>(
            out + (size_t)blockIdx.x * (K1_FILLROWS / K1_GRID) * NN);
#pragma unroll
        for (int i = 0; i < (K1_FILLROWS / K1_GRID) * (NN / 4) / K1_THREADS; i++)
            __stcs(&dst[i * K1_THREADS + tid], z);
    }

    const int row0 = blockIdx.x * 16 + warp * 2;
    const int row1 = row0 + 1;

    // load 2 feat rows (streaming) -> smem + copy to out
    const float4* fA = reinterpret_cast<const float4*>(feat + (size_t)row0 * DD);
    const float4* fB = reinterpret_cast<const float4*>(feat + (size_t)row1 * DD);
    float4 a0 = __ldcs(&fA[lane]), a1 = __ldcs(&fA[lane + 32]);
    float4 b0 = __ldcs(&fB[lane]), b1v = __ldcs(&fB[lane + 32]);
    float* rowA = &srow[warp][0];
    float* rowB = &srow[warp][DD];
    reinterpret_cast<float4*>(rowA)[lane]      = a0;
    reinterpret_cast<float4*>(rowA)[lane + 32] = a1;
    reinterpret_cast<float4*>(rowB)[lane]      = b0;
    reinterpret_cast<float4*>(rowB)[lane + 32] = b1v;
    float4* ocA = reinterpret_cast<float4*>(out + OFF_FEAT + (size_t)row0 * DD);
    float4* ocB = reinterpret_cast<float4*>(out + OFF_FEAT + (size_t)row1 * DD);
    __stcs(&ocA[lane], a0); __stcs(&ocA[lane + 32], a1);
    __stcs(&ocB[lane], b0); __stcs(&ocB[lane + 32], b1v);
    __syncwarp();

    const float4* W14 = reinterpret_cast<const float4*>(W1);  // [256][32] float4
    float4 accA = make_float4(0.f, 0.f, 0.f, 0.f);
    float4 accB = make_float4(0.f, 0.f, 0.f, 0.f);
#pragma unroll 8
    for (int k = 0; k < DD; k++) {
        float4 wv = __ldg(&W14[k * 32 + lane]);   // L1-resident after warmup
        float sA = rowA[k], sB = rowB[k];
        accA.x = fmaf(sA, wv.x, accA.x); accA.y = fmaf(sA, wv.y, accA.y);
        accA.z = fmaf(sA, wv.z, accA.z); accA.w = fmaf(sA, wv.w, accA.w);
        accB.x = fmaf(sB, wv.x, accB.x); accB.y = fmaf(sB, wv.y, accB.y);
        accB.z = fmaf(sB, wv.z, accB.z); accB.w = fmaf(sB, wv.w, accB.w);
    }
    reinterpret_cast<float4*>(g_featW + (size_t)row0 * HH)[lane] = accA;
    reinterpret_cast<float4*>(g_featW + (size_t)row1 * HH)[lane] = accB;

    if (blockIdx.x == 0 && tid == 0) {
        out[OFF_BEFORE] = 64.0f;
        out[OFF_AFTER]  = 0.0f;
    }
}

// ---------------------------------------------------------------------------
// Kernel 2: WARP-PER-ROW. 8 rows/block, grid 1024. Zero __syncthreads —
// every phase is warp-local; __syncwarp orders the fill before the scatter.
// Lane l owns edges (l, l+32). Ranking kept on p1 (sigmoid saturation ties
// must break by index exactly like the reference softmax argsort).
// ---------------------------------------------------------------------------
__global__ void __launch_bounds__(256) edge_kernel(const float* __restrict__ adj,
                                                   const int*   __restrict__ nbr,
                                                   const float* __restrict__ b1,
                                                   const float* __restrict__ prelu_a,
                                                   const float* __restrict__ W2,
                                                   const float* __restrict__ b2,
                                                   float* __restrict__ out) {
    __shared__ int   snbr[8][KK];
    __shared__ float sp1[8][KK];

    const int tid  = threadIdx.x;
    const int warp = tid >> 5;
    const int lane = tid & 31;
    const int row  = blockIdx.x * 8 + warp;

    // ---- per-lane loads (edges lane and lane+32)
    const int nlo = __ldg(&nbr[row * KK + lane]);
    const int nhi = __ldg(&nbr[row * KK + lane + 32]);
    snbr[warp][lane]      = nlo;
    snbr[warp][lane + 32] = nhi;
    const float vlo = __ldg(adj + (size_t)row * NN + nlo);
    const float vhi = __ldg(adj + (size_t)row * NN + nhi);

    const float4* fW4 = reinterpret_cast<const float4*>(g_featW);
    float4 fs = fW4[(size_t)row * 32 + lane];
    {
        float4 bb = __ldg(&reinterpret_cast<const float4*>(b1)[lane]);
        fs.x += bb.x; fs.y += bb.y; fs.z += bb.z; fs.w += bb.w;
    }

    // ---- streaming zero-fill of own row (rows not covered by kernel 1)
    if (row >= K1_FILLROWS) {
        float4* orow = reinterpret_cast<float4*>(out + (size_t)row * NN);
        const float4 z = make_float4(0.f, 0.f, 0.f, 0.f);
#pragma unroll
        for (int i = 0; i < 64; i++) __stcs(&orow[i * 32 + lane], z);
    }

    // ---- pair_list (coalesced float2 per lane, both halves)
    {
        float2* pp = reinterpret_cast<float2*>(out + OFF_PAIR) + (long long)row * KK;
        __stcs(&pp[lane],      make_float2((float)row, (float)nlo));
        __stcs(&pp[lane + 32], make_float2((float)row, (float)nhi));
    }

    // per-lane MLP invariants (4 feature dims per lane)
    const int j0 = lane * 4;
    const float a0 = __ldg(&prelu_a[j0 + 0]), a1 = __ldg(&prelu_a[j0 + 1]),
                a2 = __ldg(&prelu_a[j0 + 2]), a3 = __ldg(&prelu_a[j0 + 3]);
    const float wd0 = __ldg(&W2[(j0 + 0) * 2 + 1]) - __ldg(&W2[(j0 + 0) * 2]);
    const float wd1 = __ldg(&W2[(j0 + 1) * 2 + 1]) - __ldg(&W2[(j0 + 1) * 2]);
    const float wd2 = __ldg(&W2[(j0 + 2) * 2 + 1]) - __ldg(&W2[(j0 + 2) * 2]);
    const float wd3 = __ldg(&W2[(j0 + 3) * 2 + 1]) - __ldg(&W2[(j0 + 3) * 2]);
    const float b2d = __ldg(&b2[1]) - __ldg(&b2[0]);

    __syncwarp();   // snbr visible

    float D_lo = 0.f, D_hi = 0.f;

#pragma unroll
    for (int b = 0; b < 8; b++) {          // 8 batches of 8 edges
        float4 fd[8];
#pragma unroll
        for (int e = 0; e < 4; e++)
            fd[e] = fW4[(size_t)snbr[warp][b * 8 + e] * 32 + lane];
#pragma unroll
        for (int e = 4; e < 8; e++)
            fd[e] = fW4[(size_t)snbr[warp][b * 8 + e] * 32 + lane];

        float dd[8];
#pragma unroll
        for (int e = 0; e < 8; e++) {
            float h0 = fs.x - fd[e].x, h1 = fs.y - fd[e].y;
            float h2 = fs.z - fd[e].z, h3 = fs.w - fd[e].w;
            h0 = (h0 >= 0.f) ? h0 : a0 * h0;
            h1 = (h1 >= 0.f) ? h1 : a1 * h1;
            h2 = (h2 >= 0.f) ? h2 : a2 * h2;
            h3 = (h3 >= 0.f) ? h3 : a3 * h3;
            dd[e] = h0 * wd0 + h1 * wd1 + h2 * wd2 + h3 * wd3;
        }
#pragma unroll
        for (int off = 16; off; off >>= 1)
#pragma unroll
            for (int e = 0; e < 8; e++)
                dd[e] += __shfl_xor_sync(0xffffffffu, dd[e], off);

        // butterfly leaves each sum in ALL lanes: select the two this lane owns
#pragma unroll
        for (int e = 0; e < 8; e++) {
            const int ge = b * 8 + e;
            if (ge < 32) D_lo = (lane == ge)        ? dd[e] : D_lo;
            else         D_hi = (lane == (ge - 32)) ? dd[e] : D_hi;
        }
    }

    // sigmoid probs (== softmax of (L0,L1) to ~1 ulp; validated in R4)
    D_lo += b2d; D_hi += b2d;
    const float p1_lo = 1.0f / (1.0f + expf(-D_lo));
    const float p0_lo = 1.0f / (1.0f + expf( D_lo));
    const float p1_hi = 1.0f / (1.0f + expf(-D_hi));
    const float p0_hi = 1.0f / (1.0f + expf( D_hi));
    {
        float2* pr = reinterpret_cast<float2*>(out + OFF_PROB) + (long long)row * KK;
        __stcs(&pr[lane],      make_float2(p0_lo, p1_lo));
        __stcs(&pr[lane + 32], make_float2(p0_hi, p1_hi));
    }
    sp1[warp][lane]      = p1_lo;
    sp1[warp][lane + 32] = p1_hi;
    __syncwarp();

    // stable ascending rank for both owned edges (exact stable-argsort)
    int rank_lo = 0, rank_hi = 0;
#pragma unroll 8
    for (int j = 0; j < KK; j++) {
        float pj = sp1[warp][j];
        rank_lo += (pj < p1_lo) || (pj == p1_lo && j < lane);
        rank_hi += (pj < p1_hi) || (pj == p1_hi && j < lane + 32);
    }
    const int keep_lo = rank_lo >= 32;
    const int keep_hi = rank_hi >= 32;

    if (keep_lo)
        __stcs(&out[OFF_LEFT + (long long)row * 32 + (rank_lo - 32)],
               (float)(row * KK + lane));
    if (keep_hi)
        __stcs(&out[OFF_LEFT + (long long)row * 32 + (rank_hi - 32)],
               (float)(row * KK + lane + 32));

    // degree + nonzero-kept count (full butterfly -> result in all lanes)
    float v = (keep_lo ? vlo : 0.f) + (keep_hi ? vhi : 0.f);
    float c = (keep_lo && vlo != 0.f ? 1.f : 0.f) + (keep_hi && vhi != 0.f ? 1.f : 0.f);
#pragma unroll
    for (int off = 16; off; off >>= 1) {
        v += __shfl_xor_sync(0xffffffffu, v, off);
        c += __shfl_xor_sync(0xffffffffu, c, off);
    }
    if (lane == 0) atomicAdd(out + OFF_AFTER, c * (1.0f / 8192.0f));

    __syncwarp();   // order own-row zero-fill before scatter (bar.warp.sync fences)

    const float inv = 1.0f / (v + 1e-6f);
    if (keep_lo) __stcs(&out[(size_t)row * NN + nlo], vlo * inv);
    if (keep_hi) __stcs(&out[(size_t)row * NN + nhi], vhi * inv);
}

// ---------------------------------------------------------------------------
extern "C" void kernel_launch(void* const* d_in, const int* in_sizes, int n_in,
                              void* d_out, int out_size) {
    const float* adj = nullptr; const float* feat = nullptr;
    const int*   nbr = nullptr; const float* W1   = nullptr;
    const float* b1  = nullptr; const float* pa   = nullptr;
    const float* W2  = nullptr; const float* b2   = nullptr;

    for (int i = 0; i < n_in; i++) {
        long long s = in_sizes[i];
        if      (s == (long long)NN * NN) adj  = (const float*)d_in[i];
        else if (s == (long long)NN * DD) feat = (const float*)d_in[i];
        else if (s == (long long)NN * KK) nbr  = (const int*)d_in[i];
        else if (s == (long long)DD * HH) W1   = (const float*)d_in[i];
        else if (s == HH) { if (!b1) b1 = (const float*)d_in[i];
                            else     pa = (const float*)d_in[i]; }
        else if (s == HH * 2) W2 = (const float*)d_in[i];
        else if (s == 2)      b2 = (const float*)d_in[i];
    }

    float* out = (float*)d_out;
    featw_kernel<<<K1_GRID, K1_THREADS>>>(feat, W1, out);
    edge_kernel<<<NN / 8, 256>>>(adj, nbr, b1, pa, W2, b2, out);
}

// round 6
// speedup vs baseline: 1.1920x; 1.1920x over previous
#include <cuda_runtime.h>

#define NN 8192
#define KK 64
#define DD 256
#define HH 128
#define K1_BLOCKS   128
#define K1_THREADS  512
#define K1_FILLROWS 3072          // adj rows zero-filled by kernel 1 (96 MB)

// ---- flat fp32 output layout (concat of reference tuple) ----
#define OFF_ADJ    0LL
#define OFF_FEAT   ((long long)NN * NN)
#define OFF_PROB   (OFF_FEAT + (long long)NN * DD)
#define OFF_PAIR   (OFF_PROB + (long long)NN * KK * 2)
#define OFF_BEFORE (OFF_PAIR + (long long)NN * KK * 2)
#define OFF_AFTER  (OFF_BEFORE + 1)
#define OFF_LEFT   (OFF_AFTER + 1)

// scratch: featW = feat @ W1   [N, 128]  (4 MB, L2-resident for edge gather)
__device__ float g_featW[(size_t)NN * HH];

// ---------------------------------------------------------------------------
// Kernel 1: featW = feat @ W1.
//  - W1 (128 KB) staged into dynamic smem ONCE (proved necessary in R4/R5)
//  - 512 threads, 64 rows/block, 4 rows/warp in ONE pass:
//    per k-iter = 1 LDS.128 (w vec) + 4 scalar LDS + 16 FMA  (2x R4 density)
//  - fused: feat copy to out + 24 adj rows zero-fill per block (96 MB total)
// ---------------------------------------------------------------------------
extern __shared__ float k1_smem[];

__global__ void __launch_bounds__(K1_THREADS) featw_kernel(const float* __restrict__ feat,
                                                           const float* __restrict__ W1,
                                                           float* __restrict__ out) {
    float* sW   = k1_smem;                  // 256*128 floats = 128 KB
    float* srow = k1_smem + DD * HH;        // 16 warps * 4 rows * 256 = 64 KB

    const int tid  = threadIdx.x;
    const int warp = tid >> 5;
    const int lane = tid & 31;

    // ---- streaming zero-fill: 24 adj rows per block (768 KB), no deps
    {
        const float4 z = make_float4(0.f, 0.f, 0.f, 0.f);
        float4* dst = reinterpret_cast<float4*>(
            out + (size_t)blockIdx.x * (K1_FILLROWS / K1_BLOCKS) * NN);
#pragma unroll
        for (int i = 0; i < (K1_FILLROWS / K1_BLOCKS) * (NN / 4) / K1_THREADS; i++)
            __stcs(&dst[i * K1_THREADS + tid], z);
    }

    // ---- stage full W1: 8192 float4, 16 per thread, coalesced
    {
        const float4* W14 = reinterpret_cast<const float4*>(W1);
        float4* sW4 = reinterpret_cast<float4*>(sW);
#pragma unroll
        for (int i = 0; i < 16; i++)
            sW4[i * K1_THREADS + tid] = W14[i * K1_THREADS + tid];
    }

    // ---- load this warp's 4 feat rows -> smem (+ streaming copy to out)
    const int row0 = blockIdx.x * 64 + warp * 4;
    float* rbase = srow + warp * 4 * DD;
#pragma unroll
    for (int r = 0; r < 4; r++) {
        const float4* f4 = reinterpret_cast<const float4*>(feat + (size_t)(row0 + r) * DD);
        float4 x0 = __ldcs(&f4[lane]), x1 = __ldcs(&f4[lane + 32]);
        reinterpret_cast<float4*>(rbase + r * DD)[lane]      = x0;
        reinterpret_cast<float4*>(rbase + r * DD)[lane + 32] = x1;
        float4* oc = reinterpret_cast<float4*>(out + OFF_FEAT + (size_t)(row0 + r) * DD);
        __stcs(&oc[lane], x0); __stcs(&oc[lane + 32], x1);
    }
    __syncthreads();   // W1 staged + (warp-local) rows written

    const float4* sW4 = reinterpret_cast<const float4*>(sW);
    const float* r0 = rbase;
    const float* r1 = rbase + DD;
    const float* r2 = rbase + 2 * DD;
    const float* r3 = rbase + 3 * DD;

    float4 acc0 = make_float4(0.f, 0.f, 0.f, 0.f);
    float4 acc1 = make_float4(0.f, 0.f, 0.f, 0.f);
    float4 acc2 = make_float4(0.f, 0.f, 0.f, 0.f);
    float4 acc3 = make_float4(0.f, 0.f, 0.f, 0.f);
#pragma unroll 4
    for (int k = 0; k < DD; k++) {
        float4 wv = sW4[k * 32 + lane];
        float s0 = r0[k], s1 = r1[k], s2 = r2[k], s3 = r3[k];
        acc0.x = fmaf(s0, wv.x, acc0.x); acc0.y = fmaf(s0, wv.y, acc0.y);
        acc0.z = fmaf(s0, wv.z, acc0.z); acc0.w = fmaf(s0, wv.w, acc0.w);
        acc1.x = fmaf(s1, wv.x, acc1.x); acc1.y = fmaf(s1, wv.y, acc1.y);
        acc1.z = fmaf(s1, wv.z, acc1.z); acc1.w = fmaf(s1, wv.w, acc1.w);
        acc2.x = fmaf(s2, wv.x, acc2.x); acc2.y = fmaf(s2, wv.y, acc2.y);
        acc2.z = fmaf(s2, wv.z, acc2.z); acc2.w = fmaf(s2, wv.w, acc2.w);
        acc3.x = fmaf(s3, wv.x, acc3.x); acc3.y = fmaf(s3, wv.y, acc3.y);
        acc3.z = fmaf(s3, wv.z, acc3.z); acc3.w = fmaf(s3, wv.w, acc3.w);
    }
    reinterpret_cast<float4*>(g_featW + (size_t)(row0 + 0) * HH)[lane] = acc0;
    reinterpret_cast<float4*>(g_featW + (size_t)(row0 + 1) * HH)[lane] = acc1;
    reinterpret_cast<float4*>(g_featW + (size_t)(row0 + 2) * HH)[lane] = acc2;
    reinterpret_cast<float4*>(g_featW + (size_t)(row0 + 3) * HH)[lane] = acc3;

    if (blockIdx.x == 0 && tid == 0) {
        out[OFF_BEFORE] = 64.0f;
        out[OFF_AFTER]  = 0.0f;
    }
}

// ---------------------------------------------------------------------------
// Kernel 2: WARP-PER-ROW (R5 design, measured 62.3us). 8 rows/block, grid
// 1024, zero __syncthreads. Gathers in flights of 4 to fit 5 blocks/SM.
// Ranking on p1 with stable index tie-break (exact stable-argsort).
// ---------------------------------------------------------------------------
__global__ void __launch_bounds__(256, 5) edge_kernel(const float* __restrict__ adj,
                                                      const int*   __restrict__ nbr,
                                                      const float* __restrict__ b1,
                                                      const float* __restrict__ prelu_a,
                                                      const float* __restrict__ W2,
                                                      const float* __restrict__ b2,
                                                      float* __restrict__ out) {
    __shared__ int   snbr[8][KK];
    __shared__ float sp1[8][KK];

    const int tid  = threadIdx.x;
    const int warp = tid >> 5;
    const int lane = tid & 31;
    const int row  = blockIdx.x * 8 + warp;

    const int nlo = __ldg(&nbr[row * KK + lane]);
    const int nhi = __ldg(&nbr[row * KK + lane + 32]);
    snbr[warp][lane]      = nlo;
    snbr[warp][lane + 32] = nhi;
    const float vlo = __ldg(adj + (size_t)row * NN + nlo);
    const float vhi = __ldg(adj + (size_t)row * NN + nhi);

    const float4* fW4 = reinterpret_cast<const float4*>(g_featW);
    float4 fs = fW4[(size_t)row * 32 + lane];
    {
        float4 bb = __ldg(&reinterpret_cast<const float4*>(b1)[lane]);
        fs.x += bb.x; fs.y += bb.y; fs.z += bb.z; fs.w += bb.w;
    }

    // streaming zero-fill of own row (rows not covered by kernel 1)
    if (row >= K1_FILLROWS) {
        float4* orow = reinterpret_cast<float4*>(out + (size_t)row * NN);
        const float4 z = make_float4(0.f, 0.f, 0.f, 0.f);
#pragma unroll
        for (int i = 0; i < 64; i++) __stcs(&orow[i * 32 + lane], z);
    }

    // pair_list
    {
        float2* pp = reinterpret_cast<float2*>(out + OFF_PAIR) + (long long)row * KK;
        __stcs(&pp[lane],      make_float2((float)row, (float)nlo));
        __stcs(&pp[lane + 32], make_float2((float)row, (float)nhi));
    }

    const int j0 = lane * 4;
    const float a0 = __ldg(&prelu_a[j0 + 0]), a1 = __ldg(&prelu_a[j0 + 1]),
                a2 = __ldg(&prelu_a[j0 + 2]), a3 = __ldg(&prelu_a[j0 + 3]);
    const float wd0 = __ldg(&W2[(j0 + 0) * 2 + 1]) - __ldg(&W2[(j0 + 0) * 2]);
    const float wd1 = __ldg(&W2[(j0 + 1) * 2 + 1]) - __ldg(&W2[(j0 + 1) * 2]);
    const float wd2 = __ldg(&W2[(j0 + 2) * 2 + 1]) - __ldg(&W2[(j0 + 2) * 2]);
    const float wd3 = __ldg(&W2[(j0 + 3) * 2 + 1]) - __ldg(&W2[(j0 + 3) * 2]);
    const float b2d = __ldg(&b2[1]) - __ldg(&b2[0]);

    __syncwarp();   // snbr visible

    float D_lo = 0.f, D_hi = 0.f;

#pragma unroll
    for (int b = 0; b < 8; b++) {          // 8 batches of 8 edges
        float dd[8];
#pragma unroll
        for (int h = 0; h < 2; h++) {      // two flights of 4 gathers
            float4 fd[4];
#pragma unroll
            for (int e = 0; e < 4; e++)
                fd[e] = fW4[(size_t)snbr[warp][b * 8 + h * 4 + e] * 32 + lane];
#pragma unroll
            for (int e = 0; e < 4; e++) {
                float h0 = fs.x - fd[e].x, h1 = fs.y - fd[e].y;
                float h2 = fs.z - fd[e].z, h3 = fs.w - fd[e].w;
                h0 = (h0 >= 0.f) ? h0 : a0 * h0;
                h1 = (h1 >= 0.f) ? h1 : a1 * h1;
                h2 = (h2 >= 0.f) ? h2 : a2 * h2;
                h3 = (h3 >= 0.f) ? h3 : a3 * h3;
                dd[h * 4 + e] = h0 * wd0 + h1 * wd1 + h2 * wd2 + h3 * wd3;
            }
        }
#pragma unroll
        for (int off = 16; off; off >>= 1)
#pragma unroll
            for (int e = 0; e < 8; e++)
                dd[e] += __shfl_xor_sync(0xffffffffu, dd[e], off);

        // butterfly leaves the sum in all lanes: pick the two this lane owns
#pragma unroll
        for (int e = 0; e < 8; e++) {
            const int ge = b * 8 + e;
            if (ge < 32) D_lo = (lane == ge)        ? dd[e] : D_lo;
            else         D_hi = (lane == (ge - 32)) ? dd[e] : D_hi;
        }
    }

    // sigmoid probs (== softmax of (L0,L1) to ~1 ulp; validated R4/R5)
    D_lo += b2d; D_hi += b2d;
    const float p1_lo = 1.0f / (1.0f + expf(-D_lo));
    const float p0_lo = 1.0f / (1.0f + expf( D_lo));
    const float p1_hi = 1.0f / (1.0f + expf(-D_hi));
    const float p0_hi = 1.0f / (1.0f + expf( D_hi));
    {
        float2* pr = reinterpret_cast<float2*>(out + OFF_PROB) + (long long)row * KK;
        __stcs(&pr[lane],      make_float2(p0_lo, p1_lo));
        __stcs(&pr[lane + 32], make_float2(p0_hi, p1_hi));
    }
    sp1[warp][lane]      = p1_lo;
    sp1[warp][lane + 32] = p1_hi;
    __syncwarp();

    // stable ascending rank for both owned edges
    int rank_lo = 0, rank_hi = 0;
#pragma unroll 8
    for (int j = 0; j < KK; j++) {
        float pj = sp1[warp][j];
        rank_lo += (pj < p1_lo) || (pj == p1_lo && j < lane);
        rank_hi += (pj < p1_hi) || (pj == p1_hi && j < lane + 32);
    }
    const int keep_lo = rank_lo >= 32;
    const int keep_hi = rank_hi >= 32;

    if (keep_lo)
        __stcs(&out[OFF_LEFT + (long long)row * 32 + (rank_lo - 32)],
               (float)(row * KK + lane));
    if (keep_hi)
        __stcs(&out[OFF_LEFT + (long long)row * 32 + (rank_hi - 32)],
               (float)(row * KK + lane + 32));

    // degree + nonzero-kept count
    float v = (keep_lo ? vlo : 0.f) + (keep_hi ? vhi : 0.f);
    float c = (keep_lo && vlo != 0.f ? 1.f : 0.f) + (keep_hi && vhi != 0.f ? 1.f : 0.f);
#pragma unroll
    for (int off = 16; off; off >>= 1) {
        v += __shfl_xor_sync(0xffffffffu, v, off);
        c += __shfl_xor_sync(0xffffffffu, c, off);
    }
    if (lane == 0) atomicAdd(out + OFF_AFTER, c * (1.0f / 8192.0f));

    __syncwarp();   // order own-row zero-fill before scatter

    const float inv = 1.0f / (v + 1e-6f);
    if (keep_lo) __stcs(&out[(size_t)row * NN + nlo], vlo * inv);
    if (keep_hi) __stcs(&out[(size_t)row * NN + nhi], vhi * inv);
}

// ---------------------------------------------------------------------------
extern "C" void kernel_launch(void* const* d_in, const int* in_sizes, int n_in,
                              void* d_out, int out_size) {
    const float* adj = nullptr; const float* feat = nullptr;
    const int*   nbr = nullptr; const float* W1   = nullptr;
    const float* b1  = nullptr; const float* pa   = nullptr;
    const float* W2  = nullptr; const float* b2   = nullptr;

    for (int i = 0; i < n_in; i++) {
        long long s = in_sizes[i];
        if      (s == (long long)NN * NN) adj  = (const float*)d_in[i];
        else if (s == (long long)NN * DD) feat = (const float*)d_in[i];
        else if (s == (long long)NN * KK) nbr  = (const int*)d_in[i];
        else if (s == (long long)DD * HH) W1   = (const float*)d_in[i];
        else if (s == HH) { if (!b1) b1 = (const float*)d_in[i];
                            else     pa = (const float*)d_in[i]; }
        else if (s == HH * 2) W2 = (const float*)d_in[i];
        else if (s == 2)      b2 = (const float*)d_in[i];
    }

    float* out = (float*)d_out;
    const int k1_smem_bytes = (DD * HH + 16 * 4 * DD) * (int)sizeof(float); // 192 KB
    static int attr_done = 0;
    if (!attr_done) {
        cudaFuncSetAttribute(featw_kernel,
                             cudaFuncAttributeMaxDynamicSharedMemorySize, k1_smem_bytes);
        attr_done = 1;
    }
    featw_kernel<<<K1_BLOCKS, K1_THREADS, k1_smem_bytes>>>(feat, W1, out);
    edge_kernel<<<NN / 8, 256>>>(adj, nbr, b1, pa, W2, b2, out);
}